// round 15
// baseline (speedup 1.0000x reference)
#include <cuda_runtime.h>

// LDDMM variational RHS, sigma=0.1, N=8192, via base-ISA tensor cores
// (mma.sync m16n8k16 bf16 — no tcgen05, harness PTX target lacks 'a').
//
//   p = clamp(mom,-1,1); c = x - 0.5 (centered)
//   K'_ij = 2^(C*sj + B*(ci.cj)),  true K = 2^(C*si) * K'   (hoisted per-i)
//   GEMM: D[128x24] += K'(bf16 hi+lo) @ B^T, B rows =
//         [p_hi(3) p_lo(3) (p(x)c)_hi(9) (p(x)c)_lo(9)]
//   epilogue: dcp = scale*(Dp_hi+Dp_lo);  dmom_e = 100*scale*(ci_e*(pi.dcp') - sum_d pi_d M_de)
// Output: [dmom (N*3) | dcp (N*3)]

#define NPTS   8192
#define NT     32            // j-tiles per CTA (JSPLIT=2)
#define TPB    256
#define C_EXP2 (-72.13475204444817f)   // -50/ln2
#define B_COEF (144.26950408889634f)   // -2*C_EXP2

// smem layout (bytes). K tiles: 128 rows x 272B (136 bf16, padded for LDSM banks)
#define KT       34816
#define OFF_KH0  0
#define OFF_KH1  34816
#define OFF_KL0  69632
#define OFF_KL1  104448
#define OFF_B    139264      // 3 buffers x 6656 (24 rows x 272B)
#define OFF_J    159232      // 2 buffers x 2048
#define SMEM_TOTAL 163328

typedef unsigned long long u64;
typedef unsigned int u32;
typedef unsigned short u16;

__device__ float g_pm[2 * NPTS * 3];
__device__ float g_pc[2 * NPTS * 3];
__device__ float g_jdata[(NPTS / 2) * 8];   // per pair-slot: {c0e,c0o,c1e,c1o},{c2e,c2o,Aje,Ajo}
__device__ u16   g_B[24 * NPTS];            // feature rows x j, bf16 bits

__device__ __forceinline__ u32 smem_u32(const void* p) {
    u32 a; asm("{ .reg .u64 t; cvta.to.shared.u64 t, %1; cvt.u32.u64 %0, t; }" : "=r"(a) : "l"(p)); return a;
}
__device__ __forceinline__ float ex2a(float a) { float r; asm("ex2.approx.ftz.f32 %0, %1;" : "=f"(r) : "f"(a)); return r; }
__device__ __forceinline__ u64 fma2(u64 a, u64 b, u64 c) { u64 d; asm("fma.rn.f32x2 %0,%1,%2,%3;" : "=l"(d) : "l"(a), "l"(b), "l"(c)); return d; }
__device__ __forceinline__ u64 pack2(float lo, float hi) { u64 r; asm("mov.b64 %0,{%1,%2};" : "=l"(r) : "f"(lo), "f"(hi)); return r; }
__device__ __forceinline__ float2 unpack2(u64 v) { float2 r; asm("mov.b64 {%0,%1},%2;" : "=f"(r.x), "=f"(r.y) : "l"(v)); return r; }
__device__ __forceinline__ u16 f2bf(float f) { u16 h; asm("cvt.rn.bf16.f32 %0, %1;" : "=h"(h) : "f"(f)); return h; }
__device__ __forceinline__ float bf2f(u16 h) { return __uint_as_float(((u32)h) << 16); }

__device__ __forceinline__ void ldsm4(u32 r[4], u32 addr) {
    asm volatile("ldmatrix.sync.aligned.m8n8.x4.shared.b16 {%0,%1,%2,%3}, [%4];"
        : "=r"(r[0]), "=r"(r[1]), "=r"(r[2]), "=r"(r[3]) : "r"(addr));
}
__device__ __forceinline__ void ldsm2(u32 r[2], u32 addr) {
    asm volatile("ldmatrix.sync.aligned.m8n8.x2.shared.b16 {%0,%1}, [%2];"
        : "=r"(r[0]), "=r"(r[1]) : "r"(addr));
}
__device__ __forceinline__ void mma16816(float d[4], const u32 a[4], const u32 b[2]) {
    asm volatile("mma.sync.aligned.m16n8k16.row.col.f32.bf16.bf16.f32 "
        "{%0,%1,%2,%3},{%4,%5,%6,%7},{%8,%9},{%0,%1,%2,%3};"
        : "+f"(d[0]), "+f"(d[1]), "+f"(d[2]), "+f"(d[3])
        : "r"(a[0]), "r"(a[1]), "r"(a[2]), "r"(a[3]), "r"(b[0]), "r"(b[1]));
}

// ---------------- prologue: per-j data + feature matrix ----------------
__global__ void lddmm_prologue(const float* __restrict__ mom, const float* __restrict__ x)
{
    const int j = blockIdx.x * blockDim.x + threadIdx.x;
    if (j >= NPTS) return;
    const float c0 = x[3*j+0] - 0.5f;
    const float c1 = x[3*j+1] - 0.5f;
    const float c2 = x[3*j+2] - 0.5f;
    const float Aj = C_EXP2 * fmaf(c0, c0, fmaf(c1, c1, c2 * c2));
    const int jp = j >> 1, h = j & 1, base = jp * 8;
    g_jdata[base + 0 + h] = c0;
    g_jdata[base + 2 + h] = c1;
    g_jdata[base + 4 + h] = c2;
    g_jdata[base + 6 + h] = Aj;

    float p[3], c[3] = { c0, c1, c2 };
    p[0] = fminf(fmaxf(mom[3*j+0], -1.0f), 1.0f);
    p[1] = fminf(fmaxf(mom[3*j+1], -1.0f), 1.0f);
    p[2] = fminf(fmaxf(mom[3*j+2], -1.0f), 1.0f);
    #pragma unroll
    for (int d = 0; d < 3; ++d) {
        const u16 ph = f2bf(p[d]);
        const u16 pl = f2bf(p[d] - bf2f(ph));
        g_B[d * NPTS + j]       = ph;
        g_B[(3 + d) * NPTS + j] = pl;
        #pragma unroll
        for (int e = 0; e < 3; ++e) {
            const float q = p[d] * c[e];
            const u16 qh = f2bf(q);
            const u16 ql = f2bf(q - bf2f(qh));
            g_B[(6 + 3*d + e) * NPTS + j]  = qh;
            g_B[(15 + 3*d + e) * NPTS + j] = ql;
        }
    }
}

// ---------------- main ----------------
__global__ __launch_bounds__(TPB, 1)
void lddmm_main(const float* __restrict__ mom, const float* __restrict__ x)
{
    extern __shared__ char sm[];
    const int tid = threadIdx.x;
    const int wid = tid >> 5, lane = tid & 31;
    const int itile = blockIdx.x;        // 0..63
    const int jc    = blockIdx.y;        // 0..1
    const u32 smb = smem_u32(sm);
    const int jbase = jc * (NPTS / 2);

    // elementwise identity: 2 threads per i-row
    const int row = tid & 127;
    const int hh  = tid >> 7;
    const int iglob = itile * 128 + row;
    const float ci0 = x[3*iglob+0] - 0.5f;
    const float ci1 = x[3*iglob+1] - 0.5f;
    const float ci2 = x[3*iglob+2] - 0.5f;
    const u64 bx0 = pack2(B_COEF * ci0, B_COEF * ci0);
    const u64 bx1 = pack2(B_COEF * ci1, B_COEF * ci1);
    const u64 bx2 = pack2(B_COEF * ci2, B_COEF * ci2);

    // MMA lane geometry
    const int i0 = wid * 16;
    const u32 a_off = (u32)((i0 + (lane & 15)) * 272 + ((lane >> 4) << 4));
    const u32 b_off = (u32)((lane & 7) * 272 + (((lane >> 3) & 1) << 4));

    // ---- tile copier (j-data + B rows for tile nt into its buffers) ----
    auto copy_tile = [&](int nt) {
        const int j0 = jbase + nt * 128;
        // sJ: 128 float4 (64 slots x 2)
        if (tid < 128) {
            float4* dstJ = (float4*)(sm + OFF_J + (nt & 1) * 2048);
            const float4* srcJ = ((const float4*)g_jdata) + (j0 >> 1) * 2;
            dstJ[tid] = srcJ[tid];
        }
        // sB: 24 rows x 64 u32
        char* dstB = sm + OFF_B + (nt % 3) * 6656;
        const u32* srcB = (const u32*)g_B;
        #pragma unroll
        for (int k = 0; k < 6; ++k) {
            const int idx = tid + k * 256;        // 0..1535
            const int r = idx >> 6, cc = idx & 63;
            *(u32*)(dstB + r * 272 + cc * 4) = srcB[r * (NPTS / 2) + (j0 >> 1) + cc];
        }
    };

    copy_tile(0);
    __syncthreads();

    float d[3][4];
    #pragma unroll
    for (int nb = 0; nb < 3; ++nb)
        #pragma unroll
        for (int k = 0; k < 4; ++k) d[nb][k] = 0.0f;

    for (int t = 0; t <= NT; ++t) {
        // -- phase A: MMA tile t-1 (issue first; tensor drains under phase B) --
        if (t > 0) {
            const u32 kb = smb + (((t - 1) & 1) ? OFF_KH1 : OFF_KH0);
            const u32 lb = smb + (((t - 1) & 1) ? OFF_KL1 : OFF_KL0);
            const u32 bb = smb + OFF_B + ((t - 1) % 3) * 6656;
            #pragma unroll
            for (int kk = 0; kk < 8; ++kk) {
                u32 Ah[4], Al[4], Bf[2];
                ldsm4(Ah, kb + a_off + kk * 32);
                ldsm4(Al, lb + a_off + kk * 32);
                #pragma unroll
                for (int nb = 0; nb < 3; ++nb) {
                    ldsm2(Bf, bb + b_off + nb * (8 * 272) + kk * 32);
                    mma16816(d[nb], Ah, Bf);
                    mma16816(d[nb], Al, Bf);
                }
            }
        }
        // -- phase B: K'-compute tile t + prefetch tile t+1 --
        if (t < NT) {
            const u32 kh = smb + ((t & 1) ? OFF_KH1 : OFF_KH0);
            const u32 kl = smb + ((t & 1) ? OFF_KL1 : OFF_KL0);
            const ulonglong2* sj = (const ulonglong2*)(sm + OFF_J + (t & 1) * 2048);
            const u32 kdst = (u32)(row * 272);
            #pragma unroll 4
            for (int q = 0; q < 32; ++q) {
                const int jp = hh * 32 + q;
                const ulonglong2 v0 = sj[2 * jp + 0];
                const ulonglong2 v1 = sj[2 * jp + 1];
                const u64 arg = fma2(bx0, v0.x, fma2(bx1, v0.y, fma2(bx2, v1.x, v1.y)));
                const float2 a = unpack2(arg);
                const float k0 = ex2a(a.x), k1 = ex2a(a.y);
                u32 khb; asm("cvt.rn.bf16x2.f32 %0,%1,%2;" : "=r"(khb) : "f"(k1), "f"(k0));
                const float l0 = k0 - __uint_as_float(khb << 16);
                const float l1 = k1 - __uint_as_float(khb & 0xFFFF0000u);
                u32 klb; asm("cvt.rn.bf16x2.f32 %0,%1,%2;" : "=r"(klb) : "f"(l1), "f"(l0));
                asm volatile("st.shared.b32 [%0], %1;" :: "r"(kh + kdst + jp * 4), "r"(khb));
                asm volatile("st.shared.b32 [%0], %1;" :: "r"(kl + kdst + jp * 4), "r"(klb));
            }
            if (t + 1 < NT) copy_tile(t + 1);
        }
        __syncthreads();
    }

    // ---- epilogue: scatter D frags to smem (reuse K area), then per-row math ----
    float* sD = (float*)sm;   // 128 rows x 25 f32
    #pragma unroll
    for (int nb = 0; nb < 3; ++nb)
        #pragma unroll
        for (int k = 0; k < 4; ++k) {
            const int r = i0 + (lane >> 2) + ((k >> 1) << 3);
            const int c = nb * 8 + (lane & 3) * 2 + (k & 1);
            sD[r * 25 + c] = d[nb][k];
        }
    __syncthreads();

    if (tid < 128) {
        float D[24];
        #pragma unroll
        for (int c = 0; c < 24; ++c) D[c] = sD[tid * 25 + c];

        const float si = fmaf(ci0, ci0, fmaf(ci1, ci1, ci2 * ci2));
        const float scale = ex2a(C_EXP2 * si);
        float pi[3];
        pi[0] = fminf(fmaxf(mom[3*iglob+0], -1.0f), 1.0f);
        pi[1] = fminf(fmaxf(mom[3*iglob+1], -1.0f), 1.0f);
        pi[2] = fminf(fmaxf(mom[3*iglob+2], -1.0f), 1.0f);

        const float dcp0 = D[0] + D[3], dcp1 = D[1] + D[4], dcp2 = D[2] + D[5];
        const float pd = fmaf(pi[0], dcp0, fmaf(pi[1], dcp1, pi[2] * dcp2));
        float tm[3];
        #pragma unroll
        for (int e = 0; e < 3; ++e) {
            float s = 0.0f;
            #pragma unroll
            for (int dd = 0; dd < 3; ++dd)
                s = fmaf(pi[dd], D[6 + 3*dd + e] + D[15 + 3*dd + e], s);
            tm[e] = s;
        }
        const float ms = 100.0f * scale;
        const float ce[3] = { ci0, ci1, ci2 };
        const int base = (jc * NPTS + iglob) * 3;
        #pragma unroll
        for (int e = 0; e < 3; ++e)
            g_pm[base + e] = ms * (ce[e] * pd - tm[e]);
        g_pc[base + 0] = scale * dcp0;
        g_pc[base + 1] = scale * dcp1;
        g_pc[base + 2] = scale * dcp2;
    }
}

// ---------------- reduce: sum the 2 j-split partials ----------------
__global__ void lddmm_reduce(float* __restrict__ out)
{
    const int idx = blockIdx.x * blockDim.x + threadIdx.x;
    const int n3 = 3 * NPTS;
    if (idx >= 2 * n3) return;
    const int e = (idx < n3) ? idx : (idx - n3);
    const float* src = (idx < n3) ? g_pm : g_pc;
    out[idx] = __ldg(src + e) + __ldg(src + n3 + e);
}

extern "C" void kernel_launch(void* const* d_in, const int* in_sizes, int n_in,
                              void* d_out, int out_size)
{
    const float* mom = (const float*)d_in[0];
    const float* x   = (const float*)d_in[1];
    float* out = (float*)d_out;

    cudaFuncSetAttribute(lddmm_main, cudaFuncAttributeMaxDynamicSharedMemorySize, SMEM_TOTAL);

    lddmm_prologue<<<NPTS / 256, 256>>>(mom, x);
    lddmm_main<<<dim3(NPTS / 128, 2), TPB, SMEM_TOTAL>>>(mom, x);
    lddmm_reduce<<<(6 * NPTS + 255) / 256, 256>>>(out);
}

// round 16
// speedup vs baseline: 1.9728x; 1.9728x over previous
#include <cuda_runtime.h>

// LDDMM variational shooting RHS, Gaussian kernel sigma=0.1, N=8192, D=3.
//   p      = clamp(mom, -1, 1)
//   K_ij   = exp(-50 * |x_i - x_j|^2)
//   dcp_i  = sum_j K_ij * p_j
//   dmom_i = 100 * sum_j K_ij * (p_i . p_j) * (x_i - x_j)
// Output: [dmom (N*3) | dcp (N*3)]
//
// R16: FFMA2 kernel at the fp32 FMA roofline.
//  - centered expansion, per-i exponent factor hoisted (proven rel_err 7e-6)
//  - S accumulator eliminated: S = pi . ac  (computed in epilogue)  -> 13 ops/pair
//  - TPB=128, grid (64,16)=1024 CTAs for per-SM load balance
//  - partial results summed straight into d_out via atomicAdd (zero-init kernel first)

#define NPTS    8192
#define JSPLIT  16
#define JCHUNK  (NPTS / JSPLIT)   // 512
#define JPAIRS  (JCHUNK / 2)      // 256
#define TPB     128

#define C_EXP2  (-72.13475204444817f)   // -50 / ln(2)
#define B_COEF  (144.26950408889634f)   // -2 * C_EXP2
#define CENTER  0.5f

typedef unsigned long long u64;

__device__ __forceinline__ float ex2_approx(float a) {
    float r;
    asm("ex2.approx.ftz.f32 %0, %1;" : "=f"(r) : "f"(a));
    return r;
}
__device__ __forceinline__ u64 fma2(u64 a, u64 b, u64 c) {
    u64 d;
    asm("fma.rn.f32x2 %0, %1, %2, %3;" : "=l"(d) : "l"(a), "l"(b), "l"(c));
    return d;
}
__device__ __forceinline__ u64 mul2(u64 a, u64 b) {
    u64 d;
    asm("mul.rn.f32x2 %0, %1, %2;" : "=l"(d) : "l"(a), "l"(b));
    return d;
}
__device__ __forceinline__ u64 pack2(float lo, float hi) {
    u64 r;
    asm("mov.b64 %0, {%1, %2};" : "=l"(r) : "f"(lo), "f"(hi));
    return r;
}
__device__ __forceinline__ float2 unpack2(u64 v) {
    float2 r;
    asm("mov.b64 {%0, %1}, %2;" : "=f"(r.x), "=f"(r.y) : "l"(v));
    return r;
}
__device__ __forceinline__ float hsum2(u64 v) {
    float2 t = unpack2(v);
    return t.x + t.y;
}

__global__ void lddmm_zero_kernel(float* __restrict__ out, int n)
{
    const int idx = blockIdx.x * blockDim.x + threadIdx.x;
    if (idx < n) out[idx] = 0.0f;
}

__global__ __launch_bounds__(TPB)
void lddmm_pair_kernel(const float* __restrict__ mom,
                       const float* __restrict__ x,
                       float* __restrict__ out,
                       int N)
{
    // Per j-pair slot: 8 u64 (f32x2) = [xj0 xj1 | xj2 Aj | pj0 pj1 | pj2 pad]
    __shared__ __align__(16) u64 s[JPAIRS * 8];

    const int i  = blockIdx.x * TPB + threadIdx.x;
    const int jc = blockIdx.y;
    const int j0 = jc * JCHUNK;

    {
        float* sf = (float*)s;
        for (int t = threadIdx.x; t < JCHUNK; t += TPB) {
            const int j = j0 + t;
            const float c0 = x[3*j + 0] - CENTER;
            const float c1 = x[3*j + 1] - CENTER;
            const float c2 = x[3*j + 2] - CENTER;
            const float Aj = C_EXP2 * fmaf(c0, c0, fmaf(c1, c1, c2 * c2));
            float p0 = mom[3*j + 0], p1 = mom[3*j + 1], p2 = mom[3*j + 2];
            p0 = fminf(fmaxf(p0, -1.0f), 1.0f);
            p1 = fminf(fmaxf(p1, -1.0f), 1.0f);
            p2 = fminf(fmaxf(p2, -1.0f), 1.0f);
            const int base = (t >> 1) * 16;   // floats per pair-slot
            const int h    = t & 1;
            sf[base +  0 + h] = c0;   // xj0 lanes
            sf[base +  2 + h] = c1;   // xj1
            sf[base +  4 + h] = c2;   // xj2
            sf[base +  6 + h] = Aj;   // Aj
            sf[base +  8 + h] = p0;   // pj0
            sf[base + 10 + h] = p1;   // pj1
            sf[base + 12 + h] = p2;   // pj2
            sf[base + 14 + h] = 0.0f; // pad
        }
    }
    __syncthreads();

    if (i >= N) return;

    const float ci0 = x[3*i + 0] - CENTER;
    const float ci1 = x[3*i + 1] - CENTER;
    const float ci2 = x[3*i + 2] - CENTER;
    const float si  = fmaf(ci0, ci0, fmaf(ci1, ci1, ci2 * ci2));
    float pi0 = mom[3*i + 0], pi1 = mom[3*i + 1], pi2 = mom[3*i + 2];
    pi0 = fminf(fmaxf(pi0, -1.0f), 1.0f);
    pi1 = fminf(fmaxf(pi1, -1.0f), 1.0f);
    pi2 = fminf(fmaxf(pi2, -1.0f), 1.0f);

    // Replicated i-side packed operands (packed once, outside the loop)
    const u64 bx0 = pack2(B_COEF * ci0, B_COEF * ci0);
    const u64 bx1 = pack2(B_COEF * ci1, B_COEF * ci1);
    const u64 bx2 = pack2(B_COEF * ci2, B_COEF * ci2);
    const u64 qi0 = pack2(pi0, pi0);
    const u64 qi1 = pack2(pi1, pi1);
    const u64 qi2 = pack2(pi2, pi2);

    u64 ac0 = 0ull, ac1 = 0ull, ac2 = 0ull;   // sum K'*pj
    u64 t0  = 0ull, t1  = 0ull, t2  = 0ull;   // sum w'*cxj

    const ulonglong2* sp = (const ulonglong2*)s;

    #pragma unroll 8
    for (int t = 0; t < JPAIRS; ++t) {
        const ulonglong2 q0 = sp[4*t + 0];   // xj0, xj1
        const ulonglong2 q1 = sp[4*t + 1];   // xj2, Aj
        const ulonglong2 q2 = sp[4*t + 2];   // pj0, pj1
        const ulonglong2 q3 = sp[4*t + 3];   // pj2, pad

        // arg' = Aj + B*(ci . cj);  true exponent = arg' + C*si (applied at end)
        u64 arg = fma2(bx2, q1.x, q1.y);
        arg = fma2(bx1, q0.y, arg);
        arg = fma2(bx0, q0.x, arg);

        const float2 a = unpack2(arg);
        const u64 K = pack2(ex2_approx(a.x), ex2_approx(a.y));

        u64 pd = mul2(qi2, q3.x);
        pd = fma2(qi1, q2.y, pd);
        pd = fma2(qi0, q2.x, pd);

        ac0 = fma2(K, q2.x, ac0);
        ac1 = fma2(K, q2.y, ac1);
        ac2 = fma2(K, q3.x, ac2);

        const u64 w = mul2(K, pd);             // w' = K' * (pi.pj)
        t0 = fma2(w, q0.x, t0);
        t1 = fma2(w, q0.y, t1);
        t2 = fma2(w, q1.x, t2);
    }

    const float scale = ex2_approx(C_EXP2 * si);   // 2^(C*si) <= 1
    const float tf0 = hsum2(t0), tf1 = hsum2(t1), tf2 = hsum2(t2);
    const float af0 = hsum2(ac0), af1 = hsum2(ac1), af2 = hsum2(ac2);

    // S' = sum_j w' = pi . (sum_j K' pj) = pi . af   (S accumulator eliminated)
    const float Sf = fmaf(pi0, af0, fmaf(pi1, af1, pi2 * af2));

    const float ms = 100.0f * scale;
    const int n3 = 3 * N;
    atomicAdd(out + 3*i + 0,      ms * (ci0 * Sf - tf0));
    atomicAdd(out + 3*i + 1,      ms * (ci1 * Sf - tf1));
    atomicAdd(out + 3*i + 2,      ms * (ci2 * Sf - tf2));
    atomicAdd(out + n3 + 3*i + 0, scale * af0);
    atomicAdd(out + n3 + 3*i + 1, scale * af1);
    atomicAdd(out + n3 + 3*i + 2, scale * af2);
}

extern "C" void kernel_launch(void* const* d_in, const int* in_sizes, int n_in,
                              void* d_out, int out_size)
{
    const float* mom = (const float*)d_in[0];
    const float* x   = (const float*)d_in[1];
    float* out = (float*)d_out;

    const int N = in_sizes[1] / 3;   // 8192

    lddmm_zero_kernel<<<(out_size + 255) / 256, 256>>>(out, out_size);

    dim3 grid((N + TPB - 1) / TPB, JSPLIT);
    lddmm_pair_kernel<<<grid, TPB>>>(mom, x, out, N);
}